// round 1
// baseline (speedup 1.0000x reference)
#include <cuda_runtime.h>

#define MAXN 50000
#define DD 64

__device__ __align__(16) float g_P[MAXN * DD];     // feat @ W_rel
__device__ __align__(16) float g_L[MAXN * DD];     // feat @ (loop or evolve)
__device__ __align__(16) float g_agg[MAXN * DD];   // segment sum accumulator
__device__ float g_ssrc[MAXN];
__device__ float g_sdst[MAXN];
__device__ int   g_has[MAXN];

// ---------------------------------------------------------------------------
// Kernel 1: zero agg + has
// ---------------------------------------------------------------------------
__global__ void k_init(int N) {
    int i = blockIdx.x * blockDim.x + threadIdx.x;
    int n4 = N * 16;  // N*64 floats / 4
    if (i < n4) ((float4*)g_agg)[i] = make_float4(0.f, 0.f, 0.f, 0.f);
    if (i < N) g_has[i] = 0;
}

// ---------------------------------------------------------------------------
// Kernel 2: has[dst] = 1 for every edge (races benign: all write 1)
// ---------------------------------------------------------------------------
__global__ void k_has(const int* __restrict__ dst, int E) {
    int i = blockIdx.x * blockDim.x + threadIdx.x;
    if (i < E) g_has[dst[i]] = 1;
}

// ---------------------------------------------------------------------------
// Kernel 3: node-level precompute. One warp per node.
//   P[n]    = feat[n] @ W_rel
//   L[n]    = feat[n] @ (has[n] ? loop_w : evolve_w)
//   ssrc[n] = feat[n] . lin_w[0:64]
//   sdst[n] = feat[n] . lin_w[64:128]
// W matrices staged in smem as (col j, col j+32) float2 pairs -> 1 LDS.64
// per matrix per k instead of 2 scalar LDS.
// ---------------------------------------------------------------------------
__global__ void k_node(const float* __restrict__ feat,
                       const float* __restrict__ W_rel,
                       const float* __restrict__ lin_w,
                       const float* __restrict__ loop_w,
                       const float* __restrict__ evolve_w,
                       int N) {
    __shared__ float2 sW[2048];
    __shared__ float2 sLp[2048];
    __shared__ float2 sEv[2048];
    int tid = threadIdx.x;
    for (int idx = tid; idx < 2048; idx += blockDim.x) {
        int k = idx >> 5, j = idx & 31;
        sW[idx]  = make_float2(W_rel[k * 64 + j],    W_rel[k * 64 + j + 32]);
        sLp[idx] = make_float2(loop_w[k * 64 + j],   loop_w[k * 64 + j + 32]);
        sEv[idx] = make_float2(evolve_w[k * 64 + j], evolve_w[k * 64 + j + 32]);
    }
    __syncthreads();

    int lane = tid & 31;
    int n = (blockIdx.x * blockDim.x + tid) >> 5;
    if (n >= N) return;

    float f0 = feat[n * 64 + lane];
    float f1 = feat[n * 64 + lane + 32];

    // attention pre-scalars (both halves of lin_w), butterfly-reduced together
    float as = f0 * lin_w[lane]      + f1 * lin_w[lane + 32];
    float ad = f0 * lin_w[64 + lane] + f1 * lin_w[96 + lane];
    #pragma unroll
    for (int o = 16; o; o >>= 1) {
        as += __shfl_xor_sync(0xffffffffu, as, o);
        ad += __shfl_xor_sync(0xffffffffu, ad, o);
    }
    if (lane == 0) { g_ssrc[n] = as; g_sdst[n] = ad; }

    const float2* Ls = g_has[n] ? sLp : sEv;   // uniform within warp
    float p0 = 0.f, p1 = 0.f, l0 = 0.f, l1 = 0.f;
    #pragma unroll
    for (int k = 0; k < 32; k++) {
        float fk = __shfl_sync(0xffffffffu, f0, k);
        float2 w  = sW[k * 32 + lane];
        float2 wl = Ls[k * 32 + lane];
        p0 += fk * w.x;  p1 += fk * w.y;
        l0 += fk * wl.x; l1 += fk * wl.y;
    }
    #pragma unroll
    for (int k = 0; k < 32; k++) {
        float fk = __shfl_sync(0xffffffffu, f1, k);
        float2 w  = sW[(k + 32) * 32 + lane];
        float2 wl = Ls[(k + 32) * 32 + lane];
        p0 += fk * w.x;  p1 += fk * w.y;
        l0 += fk * wl.x; l1 += fk * wl.y;
    }
    g_P[n * 64 + lane]      = p0;
    g_P[n * 64 + lane + 32] = p1;
    g_L[n * 64 + lane]      = l0;
    g_L[n * 64 + lane + 32] = l1;
}

// ---------------------------------------------------------------------------
// Kernel 4: edge scatter. 16 threads per edge; each thread handles one
// float4 of the 64-float message row; vectorized global reduction.
//   atten = sigmoid(relu(ssrc[s] + sdst[d] + b))
//   agg[d] += atten * P[s]
// ---------------------------------------------------------------------------
__global__ void k_edge(const int* __restrict__ src,
                       const int* __restrict__ dst,
                       const float* __restrict__ lin_b,
                       int E) {
    int t = blockIdx.x * blockDim.x + threadIdx.x;
    int e = t >> 4;
    if (e >= E) return;
    int l = t & 15;
    int s = __ldg(src + e);
    int d = __ldg(dst + e);
    float x = g_ssrc[s] + g_sdst[d] + __ldg(lin_b);
    float a = (x > 0.f) ? __fdividef(1.f, 1.f + __expf(-x)) : 0.5f;
    float4 p = ((const float4*)g_P)[s * 16 + l];
    float* out = g_agg + d * 64 + l * 4;
    asm volatile("red.global.add.v4.f32 [%0], {%1,%2,%3,%4};"
                 :: "l"(out), "f"(a * p.x), "f"(a * p.y),
                    "f"(a * p.z), "f"(a * p.w)
                 : "memory");
}

// ---------------------------------------------------------------------------
// Kernel 5: finalize.  out = tanh((has ? agg : feat) * norm + L)
// ---------------------------------------------------------------------------
__global__ void k_final(const float* __restrict__ feat,
                        const float* __restrict__ norm,
                        float* __restrict__ out,
                        int N) {
    int t = blockIdx.x * blockDim.x + threadIdx.x;
    if (t >= N * 16) return;
    int n = t >> 4;
    float nm = norm[n];
    float4 b = g_has[n] ? ((const float4*)g_agg)[t]
                        : ((const float4*)feat)[t];
    float4 L = ((const float4*)g_L)[t];
    float4 o;
    o.x = tanhf(b.x * nm + L.x);
    o.y = tanhf(b.y * nm + L.y);
    o.z = tanhf(b.z * nm + L.z);
    o.w = tanhf(b.w * nm + L.w);
    ((float4*)out)[t] = o;
}

// ---------------------------------------------------------------------------
extern "C" void kernel_launch(void* const* d_in, const int* in_sizes, int n_in,
                              void* d_out, int out_size) {
    const float* feat   = (const float*)d_in[0];
    const float* norm   = (const float*)d_in[1];
    const int*   esrc   = (const int*)d_in[2];
    const int*   edst   = (const int*)d_in[3];
    /* d_in[4] = etype : unused (no-op permutation in reference) */
    const float* W_rel  = (const float*)d_in[5];
    const float* lin_w  = (const float*)d_in[6];
    const float* lin_b  = (const float*)d_in[7];
    const float* loop_w = (const float*)d_in[8];
    const float* evolve = (const float*)d_in[9];

    int N = in_sizes[1];   // norm: [N]
    int E = in_sizes[2];   // edge_src: [E]

    k_init<<<(N * 16 + 255) / 256, 256>>>(N);
    k_has<<<(E + 255) / 256, 256>>>(edst, E);
    k_node<<<(N + 7) / 8, 256>>>(feat, W_rel, lin_w, loop_w, evolve, N);
    {
        long long threads = (long long)E * 16;
        int grid = (int)((threads + 255) / 256);
        k_edge<<<grid, 256>>>(esrc, edst, lin_b, E);
    }
    k_final<<<(N * 16 + 255) / 256, 256>>>(feat, norm, (float*)d_out, N);
}

// round 5
// speedup vs baseline: 1.2065x; 1.2065x over previous
#include <cuda_runtime.h>

#define MAXN 50000
#define DD 64
#define NPW 4   // nodes per warp in k_node

__device__ __align__(16) float g_P[MAXN * DD];     // feat @ W_rel
__device__ __align__(16) float g_L[MAXN * DD];     // feat @ (loop or evolve)
__device__ __align__(16) float g_agg[MAXN * DD];   // segment sum accumulator
__device__ float g_ssrc[MAXN];
__device__ float g_sdst[MAXN];
__device__ int   g_has[MAXN];

// ---------------------------------------------------------------------------
// Kernel 1: zero agg + has
// ---------------------------------------------------------------------------
__global__ void k_init(int N) {
    int i = blockIdx.x * blockDim.x + threadIdx.x;
    int n4 = N * 16;  // N*64 floats / 4
    if (i < n4) ((float4*)g_agg)[i] = make_float4(0.f, 0.f, 0.f, 0.f);
    if (i < N) g_has[i] = 0;
}

// ---------------------------------------------------------------------------
// Kernel 2: has[dst] = 1 for every edge (races benign: all write 1)
// ---------------------------------------------------------------------------
__global__ void k_has(const int* __restrict__ dst, int E) {
    int i = blockIdx.x * blockDim.x + threadIdx.x;
    if (i < E) g_has[dst[i]] = 1;
}

// ---------------------------------------------------------------------------
// Kernel 3: node precompute, persistent grid, 4 nodes per warp.
//   P[n]    = feat[n] @ W_rel
//   L[n]    = feat[n] @ (has[n] ? loop_w : evolve_w)
//   ssrc[n] = feat[n].lin_w[0:64],  sdst[n] = feat[n].lin_w[64:128]
// Weight matrices staged ONCE per block in smem as (col j, col j+32) float2
// pairs; each LDS.64 feeds 4 nodes' FFMAs (4x less smem traffic than R1).
// ---------------------------------------------------------------------------
__global__ void k_node(const float* __restrict__ feat,
                       const float* __restrict__ W_rel,
                       const float* __restrict__ lin_w,
                       const float* __restrict__ loop_w,
                       const float* __restrict__ evolve_w,
                       int N) {
    __shared__ float2 sW[2048];
    __shared__ float2 sLp[2048];
    __shared__ float2 sEv[2048];
    int tid = threadIdx.x;
    for (int idx = tid; idx < 2048; idx += blockDim.x) {
        int k = idx >> 5, j = idx & 31;
        sW[idx]  = make_float2(W_rel[k * 64 + j],    W_rel[k * 64 + j + 32]);
        sLp[idx] = make_float2(loop_w[k * 64 + j],   loop_w[k * 64 + j + 32]);
        sEv[idx] = make_float2(evolve_w[k * 64 + j], evolve_w[k * 64 + j + 32]);
    }
    __syncthreads();

    int lane = tid & 31;
    int warpsPerBlock = blockDim.x >> 5;
    int gwarp = blockIdx.x * warpsPerBlock + (tid >> 5);
    int totalWarps = gridDim.x * warpsPerBlock;
    int ngroups = (N + NPW - 1) / NPW;

    float lw0 = lin_w[lane],      lw1 = lin_w[lane + 32];
    float lw2 = lin_w[64 + lane], lw3 = lin_w[96 + lane];

    for (int g = gwarp; g < ngroups; g += totalWarps) {
        int n0 = g * NPW;
        float f0[NPW], f1[NPW];
        #pragma unroll
        for (int j = 0; j < NPW; j++) {
            int n = n0 + j;
            if (n < N) {
                f0[j] = feat[n * 64 + lane];
                f1[j] = feat[n * 64 + lane + 32];
            } else { f0[j] = 0.f; f1[j] = 0.f; }
        }

        // attention pre-scalars
        float as[NPW], ad[NPW];
        #pragma unroll
        for (int j = 0; j < NPW; j++) {
            as[j] = f0[j] * lw0 + f1[j] * lw1;
            ad[j] = f0[j] * lw2 + f1[j] * lw3;
        }
        #pragma unroll
        for (int o = 16; o; o >>= 1) {
            #pragma unroll
            for (int j = 0; j < NPW; j++) {
                as[j] += __shfl_xor_sync(0xffffffffu, as[j], o);
                ad[j] += __shfl_xor_sync(0xffffffffu, ad[j], o);
            }
        }
        if (lane == 0) {
            #pragma unroll
            for (int j = 0; j < NPW; j++) {
                int n = n0 + j;
                if (n < N) { g_ssrc[n] = as[j]; g_sdst[n] = ad[j]; }
            }
        }

        float2 p[NPW], lp[NPW], le[NPW];
        #pragma unroll
        for (int j = 0; j < NPW; j++) {
            p[j]  = make_float2(0.f, 0.f);
            lp[j] = make_float2(0.f, 0.f);
            le[j] = make_float2(0.f, 0.f);
        }

        #pragma unroll
        for (int k = 0; k < 32; k++) {
            float2 w  = sW[k * 32 + lane];
            float2 wl = sLp[k * 32 + lane];
            float2 we = sEv[k * 32 + lane];
            #pragma unroll
            for (int j = 0; j < NPW; j++) {
                float fk = __shfl_sync(0xffffffffu, f0[j], k);
                p[j].x  += fk * w.x;  p[j].y  += fk * w.y;
                lp[j].x += fk * wl.x; lp[j].y += fk * wl.y;
                le[j].x += fk * we.x; le[j].y += fk * we.y;
            }
        }
        #pragma unroll
        for (int k = 0; k < 32; k++) {
            float2 w  = sW[(k + 32) * 32 + lane];
            float2 wl = sLp[(k + 32) * 32 + lane];
            float2 we = sEv[(k + 32) * 32 + lane];
            #pragma unroll
            for (int j = 0; j < NPW; j++) {
                float fk = __shfl_sync(0xffffffffu, f1[j], k);
                p[j].x  += fk * w.x;  p[j].y  += fk * w.y;
                lp[j].x += fk * wl.x; lp[j].y += fk * wl.y;
                le[j].x += fk * we.x; le[j].y += fk * we.y;
            }
        }

        #pragma unroll
        for (int j = 0; j < NPW; j++) {
            int n = n0 + j;
            if (n < N) {
                g_P[n * 64 + lane]      = p[j].x;
                g_P[n * 64 + lane + 32] = p[j].y;
                float2 L = g_has[n] ? lp[j] : le[j];
                g_L[n * 64 + lane]      = L.x;
                g_L[n * 64 + lane + 32] = L.y;
            }
        }
    }
}

// ---------------------------------------------------------------------------
// Kernel 4: edge scatter. Warp = 2 edges, 16 threads each. Leader lanes
// (0 and 16) load the per-edge scalars + compute attention once, broadcast
// via shfl — 16x fewer scalar LDGs than one-load-per-thread.
// ---------------------------------------------------------------------------
__global__ void k_edge(const int* __restrict__ src,
                       const int* __restrict__ dst,
                       const float* __restrict__ lin_b,
                       int E) {
    int t = blockIdx.x * blockDim.x + threadIdx.x;
    int warp = t >> 5;
    int lane = t & 31;
    int half = lane >> 4;          // 0 or 1
    int l = lane & 15;             // float4 slot within the 64-float row
    int e = warp * 2 + half;
    bool valid = (e < E);

    int s = 0, d = 0;
    float a = 0.f;
    if (l == 0 && valid) {
        s = __ldg(src + e);
        d = __ldg(dst + e);
        float x = g_ssrc[s] + g_sdst[d] + __ldg(lin_b);
        a = (x > 0.f) ? __fdividef(1.f, 1.f + __expf(-x)) : 0.5f;
    }
    int leader = lane & 16;
    s = __shfl_sync(0xffffffffu, s, leader);
    d = __shfl_sync(0xffffffffu, d, leader);
    a = __shfl_sync(0xffffffffu, a, leader);
    if (!valid) return;

    float4 p = ((const float4*)g_P)[s * 16 + l];
    float* out = g_agg + d * 64 + l * 4;
    asm volatile("red.global.add.v4.f32 [%0], {%1,%2,%3,%4};"
                 :: "l"(out), "f"(a * p.x), "f"(a * p.y),
                    "f"(a * p.z), "f"(a * p.w)
                 : "memory");
}

// ---------------------------------------------------------------------------
// Kernel 5: finalize.  out = tanh((has ? agg : feat) * norm + L)
// ---------------------------------------------------------------------------
__global__ void k_final(const float* __restrict__ feat,
                        const float* __restrict__ norm,
                        float* __restrict__ out,
                        int N) {
    int t = blockIdx.x * blockDim.x + threadIdx.x;
    if (t >= N * 16) return;
    int n = t >> 4;
    float nm = norm[n];
    float4 b = g_has[n] ? ((const float4*)g_agg)[t]
                        : ((const float4*)feat)[t];
    float4 L = ((const float4*)g_L)[t];
    float4 o;
    o.x = tanhf(b.x * nm + L.x);
    o.y = tanhf(b.y * nm + L.y);
    o.z = tanhf(b.z * nm + L.z);
    o.w = tanhf(b.w * nm + L.w);
    ((float4*)out)[t] = o;
}

// ---------------------------------------------------------------------------
extern "C" void kernel_launch(void* const* d_in, const int* in_sizes, int n_in,
                              void* d_out, int out_size) {
    const float* feat   = (const float*)d_in[0];
    const float* norm   = (const float*)d_in[1];
    const int*   esrc   = (const int*)d_in[2];
    const int*   edst   = (const int*)d_in[3];
    /* d_in[4] = etype : unused (no-op permutation in reference) */
    const float* W_rel  = (const float*)d_in[5];
    const float* lin_w  = (const float*)d_in[6];
    const float* lin_b  = (const float*)d_in[7];
    const float* loop_w = (const float*)d_in[8];
    const float* evolve = (const float*)d_in[9];

    int N = in_sizes[1];   // norm: [N]
    int E = in_sizes[2];   // edge_src: [E]

    k_init<<<(N * 16 + 255) / 256, 256>>>(N);
    k_has<<<(E + 255) / 256, 256>>>(edst, E);
    k_node<<<592, 256>>>(feat, W_rel, lin_w, loop_w, evolve, N);
    {
        long long threads = (long long)E * 16;
        int grid = (int)((threads + 255) / 256);
        k_edge<<<grid, 256>>>(esrc, edst, lin_b, E);
    }
    k_final<<<(N * 16 + 255) / 256, 256>>>(feat, norm, (float*)d_out, N);
}

// round 9
// speedup vs baseline: 1.3404x; 1.1110x over previous
#include <cuda_runtime.h>

#define MAXN 50000
#define MAXE 1600000
#define DD 64
#define NPW 4   // nodes per warp in k_node

__device__ __align__(16) float g_P[MAXN * DD];     // feat @ W_rel
__device__ __align__(16) float g_L[MAXN * DD];     // feat @ (loop or evolve)
__device__ __align__(16) float g_agg[MAXN * DD];   // segment sum accumulator
__device__ __align__(16) float g_att[MAXE];        // per-edge attention
__device__ float g_ssrc[MAXN];
__device__ float g_sdst[MAXN];
__device__ int   g_has[MAXN];

// packed f32x2 FMA: acc = a*b + acc (both lanes)
__device__ __forceinline__ void ffma2(unsigned long long& acc,
                                      unsigned long long a,
                                      unsigned long long b) {
    asm("fma.rn.f32x2 %0, %1, %2, %0;" : "+l"(acc) : "l"(a), "l"(b));
}
__device__ __forceinline__ unsigned long long pack2(float v) {
    unsigned long long r;
    unsigned int u = __float_as_uint(v);
    asm("mov.b64 %0, {%1, %1};" : "=l"(r) : "r"(u));
    return r;
}

// ---------------------------------------------------------------------------
// Kernel 1: zero agg + has
// ---------------------------------------------------------------------------
__global__ void k_init(int N) {
    int i = blockIdx.x * blockDim.x + threadIdx.x;
    int n4 = N * 16;
    if (i < n4) ((float4*)g_agg)[i] = make_float4(0.f, 0.f, 0.f, 0.f);
    if (i < N) g_has[i] = 0;
}

// ---------------------------------------------------------------------------
// Kernel 2: has[dst] = 1 (races benign)
// ---------------------------------------------------------------------------
__global__ void k_has(const int* __restrict__ dst, int E) {
    int i = blockIdx.x * blockDim.x + threadIdx.x;
    if (i < E) g_has[dst[i]] = 1;
}

// ---------------------------------------------------------------------------
// Kernel 3: node precompute, persistent grid, 4 nodes/warp, packed f32x2 FMA.
// ---------------------------------------------------------------------------
__global__ void k_node(const float* __restrict__ feat,
                       const float* __restrict__ W_rel,
                       const float* __restrict__ lin_w,
                       const float* __restrict__ loop_w,
                       const float* __restrict__ evolve_w,
                       int N) {
    __shared__ float2 sW[2048];
    __shared__ float2 sLp[2048];
    __shared__ float2 sEv[2048];
    int tid = threadIdx.x;
    for (int idx = tid; idx < 2048; idx += blockDim.x) {
        int k = idx >> 5, j = idx & 31;
        sW[idx]  = make_float2(W_rel[k * 64 + j],    W_rel[k * 64 + j + 32]);
        sLp[idx] = make_float2(loop_w[k * 64 + j],   loop_w[k * 64 + j + 32]);
        sEv[idx] = make_float2(evolve_w[k * 64 + j], evolve_w[k * 64 + j + 32]);
    }
    __syncthreads();

    const unsigned long long* sWu  = (const unsigned long long*)sW;
    const unsigned long long* sLpu = (const unsigned long long*)sLp;
    const unsigned long long* sEvu = (const unsigned long long*)sEv;

    int lane = tid & 31;
    int warpsPerBlock = blockDim.x >> 5;
    int gwarp = blockIdx.x * warpsPerBlock + (tid >> 5);
    int totalWarps = gridDim.x * warpsPerBlock;
    int ngroups = (N + NPW - 1) / NPW;

    float lw0 = lin_w[lane],      lw1 = lin_w[lane + 32];
    float lw2 = lin_w[64 + lane], lw3 = lin_w[96 + lane];

    for (int g = gwarp; g < ngroups; g += totalWarps) {
        int n0 = g * NPW;
        float f0[NPW], f1[NPW];
        #pragma unroll
        for (int j = 0; j < NPW; j++) {
            int n = n0 + j;
            if (n < N) {
                f0[j] = feat[n * 64 + lane];
                f1[j] = feat[n * 64 + lane + 32];
            } else { f0[j] = 0.f; f1[j] = 0.f; }
        }

        float as[NPW], ad[NPW];
        #pragma unroll
        for (int j = 0; j < NPW; j++) {
            as[j] = f0[j] * lw0 + f1[j] * lw1;
            ad[j] = f0[j] * lw2 + f1[j] * lw3;
        }
        #pragma unroll
        for (int o = 16; o; o >>= 1) {
            #pragma unroll
            for (int j = 0; j < NPW; j++) {
                as[j] += __shfl_xor_sync(0xffffffffu, as[j], o);
                ad[j] += __shfl_xor_sync(0xffffffffu, ad[j], o);
            }
        }
        if (lane == 0) {
            #pragma unroll
            for (int j = 0; j < NPW; j++) {
                int n = n0 + j;
                if (n < N) { g_ssrc[n] = as[j]; g_sdst[n] = ad[j]; }
            }
        }

        unsigned long long p[NPW], lp[NPW], le[NPW];
        #pragma unroll
        for (int j = 0; j < NPW; j++) { p[j] = 0ULL; lp[j] = 0ULL; le[j] = 0ULL; }

        #pragma unroll
        for (int k = 0; k < 32; k++) {
            unsigned long long w  = sWu[k * 32 + lane];
            unsigned long long wl = sLpu[k * 32 + lane];
            unsigned long long we = sEvu[k * 32 + lane];
            #pragma unroll
            for (int j = 0; j < NPW; j++) {
                unsigned long long fk2 = pack2(__shfl_sync(0xffffffffu, f0[j], k));
                ffma2(p[j], fk2, w);
                ffma2(lp[j], fk2, wl);
                ffma2(le[j], fk2, we);
            }
        }
        #pragma unroll
        for (int k = 0; k < 32; k++) {
            unsigned long long w  = sWu[(k + 32) * 32 + lane];
            unsigned long long wl = sLpu[(k + 32) * 32 + lane];
            unsigned long long we = sEvu[(k + 32) * 32 + lane];
            #pragma unroll
            for (int j = 0; j < NPW; j++) {
                unsigned long long fk2 = pack2(__shfl_sync(0xffffffffu, f1[j], k));
                ffma2(p[j], fk2, w);
                ffma2(lp[j], fk2, wl);
                ffma2(le[j], fk2, we);
            }
        }

        #pragma unroll
        for (int j = 0; j < NPW; j++) {
            int n = n0 + j;
            if (n < N) {
                union { unsigned long long u; float2 f; } cp, cl, ce;
                cp.u = p[j]; cl.u = lp[j]; ce.u = le[j];
                g_P[n * 64 + lane]      = cp.f.x;
                g_P[n * 64 + lane + 32] = cp.f.y;
                float2 L = g_has[n] ? cl.f : ce.f;
                g_L[n * 64 + lane]      = L.x;
                g_L[n * 64 + lane + 32] = L.y;
            }
        }
    }
}

// ---------------------------------------------------------------------------
// Kernel 3.5: per-edge attention. 4 edges/thread, coalesced int4/float4,
// 8 independent scalar gathers in flight.
// ---------------------------------------------------------------------------
__device__ __forceinline__ float sigrelu(float x) {
    return (x > 0.f) ? __fdividef(1.f, 1.f + __expf(-x)) : 0.5f;
}

__global__ void k_att(const int* __restrict__ src,
                      const int* __restrict__ dst,
                      const float* __restrict__ lin_b,
                      int E) {
    int i = blockIdx.x * blockDim.x + threadIdx.x;
    int e = i * 4;
    float b = __ldg(lin_b);
    if (e + 3 < E) {
        int4 s4 = *(const int4*)(src + e);
        int4 d4 = *(const int4*)(dst + e);
        float sx = g_ssrc[s4.x], sy = g_ssrc[s4.y],
              sz = g_ssrc[s4.z], sw = g_ssrc[s4.w];
        float dx = g_sdst[d4.x], dy = g_sdst[d4.y],
              dz = g_sdst[d4.z], dw = g_sdst[d4.w];
        float4 o;
        o.x = sigrelu(sx + dx + b);
        o.y = sigrelu(sy + dy + b);
        o.z = sigrelu(sz + dz + b);
        o.w = sigrelu(sw + dw + b);
        *(float4*)(g_att + e) = o;
    } else {
        for (int k = e; k < E; k++)
            g_att[k] = sigrelu(g_ssrc[src[k]] + g_sdst[dst[k]] + b);
    }
}

// ---------------------------------------------------------------------------
// Kernel 4: edge scatter. Warp = 4 edges (2 per 16-lane half, unroll 2).
// All per-edge scalar loads (s, d, a) are independent (att precomputed),
// both P gathers issued back-to-back -> 2 dependent levels, MLP 2.
// ---------------------------------------------------------------------------
__global__ void k_edge(const int* __restrict__ src,
                       const int* __restrict__ dst,
                       int E) {
    int t = blockIdx.x * blockDim.x + threadIdx.x;
    int warp = t >> 5;
    int lane = t & 31;
    int half = lane >> 4;
    int l = lane & 15;

    int e0 = warp * 4 + half;
    int e1 = e0 + 2;
    bool v0 = (e0 < E), v1 = (e1 < E);

    int s0 = 0, d0 = 0, s1 = 0, d1 = 0;
    float a0 = 0.f, a1 = 0.f;
    if (v0) { s0 = __ldg(src + e0); d0 = __ldg(dst + e0); a0 = __ldg(g_att + e0); }
    if (v1) { s1 = __ldg(src + e1); d1 = __ldg(dst + e1); a1 = __ldg(g_att + e1); }

    float4 p0 = make_float4(0.f,0.f,0.f,0.f), p1 = p0;
    if (v0) p0 = ((const float4*)g_P)[s0 * 16 + l];
    if (v1) p1 = ((const float4*)g_P)[s1 * 16 + l];

    if (v0) {
        float* out = g_agg + d0 * 64 + l * 4;
        asm volatile("red.global.add.v4.f32 [%0], {%1,%2,%3,%4};"
                     :: "l"(out), "f"(a0 * p0.x), "f"(a0 * p0.y),
                        "f"(a0 * p0.z), "f"(a0 * p0.w) : "memory");
    }
    if (v1) {
        float* out = g_agg + d1 * 64 + l * 4;
        asm volatile("red.global.add.v4.f32 [%0], {%1,%2,%3,%4};"
                     :: "l"(out), "f"(a1 * p1.x), "f"(a1 * p1.y),
                        "f"(a1 * p1.z), "f"(a1 * p1.w) : "memory");
    }
}

// ---------------------------------------------------------------------------
// Kernel 5: finalize.  out = tanh((has ? agg : feat) * norm + L)
// ---------------------------------------------------------------------------
__global__ void k_final(const float* __restrict__ feat,
                        const float* __restrict__ norm,
                        float* __restrict__ out,
                        int N) {
    int t = blockIdx.x * blockDim.x + threadIdx.x;
    if (t >= N * 16) return;
    int n = t >> 4;
    float nm = norm[n];
    float4 b = g_has[n] ? ((const float4*)g_agg)[t]
                        : ((const float4*)feat)[t];
    float4 L = ((const float4*)g_L)[t];
    float4 o;
    o.x = tanhf(b.x * nm + L.x);
    o.y = tanhf(b.y * nm + L.y);
    o.z = tanhf(b.z * nm + L.z);
    o.w = tanhf(b.w * nm + L.w);
    ((float4*)out)[t] = o;
}

// ---------------------------------------------------------------------------
extern "C" void kernel_launch(void* const* d_in, const int* in_sizes, int n_in,
                              void* d_out, int out_size) {
    const float* feat   = (const float*)d_in[0];
    const float* norm   = (const float*)d_in[1];
    const int*   esrc   = (const int*)d_in[2];
    const int*   edst   = (const int*)d_in[3];
    /* d_in[4] = etype : unused (no-op permutation in reference) */
    const float* W_rel  = (const float*)d_in[5];
    const float* lin_w  = (const float*)d_in[6];
    const float* lin_b  = (const float*)d_in[7];
    const float* loop_w = (const float*)d_in[8];
    const float* evolve = (const float*)d_in[9];

    int N = in_sizes[1];   // norm: [N]
    int E = in_sizes[2];   // edge_src: [E]

    k_init<<<(N * 16 + 255) / 256, 256>>>(N);
    k_has<<<(E + 255) / 256, 256>>>(edst, E);
    k_node<<<592, 256>>>(feat, W_rel, lin_w, loop_w, evolve, N);
    k_att<<<((E + 3) / 4 + 255) / 256, 256>>>(esrc, edst, lin_b, E);
    {
        // one warp per 4 edges
        long long warps = (E + 3) / 4;
        int grid = (int)((warps * 32 + 255) / 256);
        k_edge<<<grid, 256>>>(esrc, edst, E);
    }
    k_final<<<(N * 16 + 255) / 256, 256>>>(feat, norm, (float*)d_out, N);
}